// round 12
// baseline (speedup 1.0000x reference)
#include <cuda_runtime.h>
#include <cuda_fp16.h>
#include <stdint.h>
#include <math.h>

#define NR 8192
#define KD 512
#define TM 128
#define KC 32                      // f16 k-chunk: 64 B/row
#define NCH (KD / KC)              // 16 K-chunks
#define NB (NR / TM)               // 64 row blocks
#define NTILES (NB * (NB + 1) / 2) // 2080 upper-triangle tiles
#define ROWB 64                    // SW64-swizzled row stride
#define NSTG 3                     // pipeline stages
#define STG_BYTES (2 * TM * ROWB)  // A+B per stage = 16 KB
#define TAU_INV 0.01f

__device__ double g_acc;
__device__ float g_sq[NR];
__device__ __half g_zb[(size_t)NR * KD];   // f16, 8 MB

#define SW64(off) ((off) ^ (((off) >> 3) & 0x30))

// ---------------- helpers ----------------
__device__ __forceinline__ uint32_t smem_u32(const void* p) {
    uint32_t a;
    asm("{ .reg .u64 t; cvta.to.shared.u64 t, %1; cvt.u32.u64 %0, t; }"
        : "=r"(a) : "l"(p));
    return a;
}
__device__ __forceinline__ void cp_async16(uint32_t s, const void* g) {
    asm volatile("cp.async.cg.shared.global [%0], [%1], 16;" :: "r"(s), "l"(g));
}
#define CP_COMMIT() asm volatile("cp.async.commit_group;" ::: "memory")
#define CP_WAIT1()  asm volatile("cp.async.wait_group 1;" ::: "memory")

__device__ __forceinline__ void ldm_x4(uint32_t* r, uint32_t a) {
    asm volatile("ldmatrix.sync.aligned.m8n8.x4.shared.b16 {%0,%1,%2,%3}, [%4];"
        : "=r"(r[0]), "=r"(r[1]), "=r"(r[2]), "=r"(r[3]) : "r"(a));
}
__device__ __forceinline__ void mma_f16acc(uint32_t* d, const uint32_t* a, const uint32_t* b) {
    asm volatile(
        "mma.sync.aligned.m16n8k16.row.col.f16.f16.f16.f16 "
        "{%0,%1}, {%2,%3,%4,%5}, {%6,%7}, {%0,%1};"
        : "+r"(d[0]), "+r"(d[1])
        : "r"(a[0]), "r"(a[1]), "r"(a[2]), "r"(a[3]), "r"(b[0]), "r"(b[1]));
}

// ---------------- Kernel 1: convert to f16 + fp32 row norms (1 warp/row) ----------------
__global__ void __launch_bounds__(256) prep_kernel(const float* __restrict__ z) {
    const int w = threadIdx.x >> 5, lane = threadIdx.x & 31;
    const int row = blockIdx.x * 8 + w;
    const float4* zr = (const float4*)(z + (size_t)row * KD);
    __half2* dst = (__half2*)(g_zb + (size_t)row * KD);
    float s = 0.0f;
    #pragma unroll
    for (int i = 0; i < 4; i++) {
        const float4 v = zr[lane + 32 * i];
        s += v.x * v.x + v.y * v.y + v.z * v.z + v.w * v.w;
        dst[2 * (lane + 32 * i)]     = __floats2half2_rn(v.x, v.y);
        dst[2 * (lane + 32 * i) + 1] = __floats2half2_rn(v.z, v.w);
    }
    #pragma unroll
    for (int o = 16; o > 0; o >>= 1) s += __shfl_down_sync(0xffffffffu, s, o);
    if (lane == 0) {
        g_sq[row] = s;
        if (row == 0) g_acc = 0.0;
    }
}

// ---------------- Kernel 2: 3-stage pipelined f16-accum HMMA GEMM ----------------
__global__ void __launch_bounds__(128) pair_mma_kernel() {
    extern __shared__ __align__(16) char dsm[];          // NSTG * 16 KB
    __shared__ float s_sqi[TM], s_sqj[TM];
    __shared__ float s_red[4];

    const int tid = threadIdx.x;
    const int wid = tid >> 5;         // 0..3
    const int lid = tid & 31;
    const int wr = wid >> 1;          // warp row 0..1 (64 rows)
    const int wc = wid & 1;           // warp col 0..1 (64 cols)

    int t = blockIdx.x, bi = 0;
    while (t >= NB - bi) { t -= NB - bi; bi++; }
    const int bj = bi + t;

    const __half* Ag = g_zb + (size_t)(bi * TM) * KD;
    const __half* Bg = g_zb + (size_t)(bj * TM) * KD;

    uint32_t smA[NSTG], smB[NSTG];
    const uint32_t dbase = smem_u32(dsm);
    #pragma unroll
    for (int s = 0; s < NSTG; s++) {
        smA[s] = dbase + s * STG_BYTES;
        smB[s] = dbase + s * STG_BYTES + TM * ROWB;
    }

    // chunk = 128 rows x 64 B per matrix = 512 x 16B units; 4 slots/thread/matrix
    auto load_chunk = [&](int kc, int st) {
        #pragma unroll
        for (int i = 0; i < 4; i++) {
            const int f = tid + (i << 7);
            const int r = f >> 2, u = f & 3;
            const uint32_t so = SW64((uint32_t)r * ROWB + (uint32_t)u * 16);
            const size_t go = (size_t)r * KD + (size_t)kc * KC + (size_t)u * 8;
            cp_async16(smA[st] + so, Ag + go);
            cp_async16(smB[st] + so, Bg + go);
        }
    };

    uint32_t d[4][8][2];
    #pragma unroll
    for (int mi = 0; mi < 4; mi++)
        #pragma unroll
        for (int ni = 0; ni < 8; ni++) {
            d[mi][ni][0] = 0u;
            d[mi][ni][1] = 0u;
        }

    load_chunk(0, 0); CP_COMMIT();
    load_chunk(1, 1); CP_COMMIT();

    const int a_row = (lid & 15);
    const int a_jofs = (lid >> 4);
    const int b_row = (lid & 7) + ((lid >> 4) << 3);
    const int b_jofs = ((lid >> 3) & 1);

    for (int kc = 0; kc < NCH; kc++) {
        CP_WAIT1();                    // chunk kc landed (unconditional commits below)
        __syncthreads();               // all warps done with stage (kc+2)%NSTG's old data
        if (kc + 2 < NCH) load_chunk(kc + 2, (kc + 2) % NSTG);
        CP_COMMIT();                   // always commit (empty group keeps accounting)

        const int st = kc % NSTG;
        #pragma unroll
        for (int kk = 0; kk < 2; kk++) {
            uint32_t afr[4][4];
            #pragma unroll
            for (int mi = 0; mi < 4; mi++) {
                const int r = wr * 64 + mi * 16 + a_row;
                ldm_x4(afr[mi], smA[st] +
                       SW64((uint32_t)r * ROWB + (uint32_t)(kk * 2 + a_jofs) * 16));
            }
            uint32_t bfr[16];
            #pragma unroll
            for (int nb = 0; nb < 4; nb++) {
                const int n = wc * 64 + nb * 16 + b_row;
                ldm_x4(bfr + nb * 4, smB[st] +
                       SW64((uint32_t)n * ROWB + (uint32_t)(kk * 2 + b_jofs) * 16));
            }
            #pragma unroll
            for (int mi = 0; mi < 4; mi++)
                #pragma unroll
                for (int ni = 0; ni < 8; ni++)
                    mma_f16acc(d[mi][ni], afr[mi], bfr + ni * 2);
        }
    }

    s_sqi[tid] = g_sq[bi * TM + tid];
    s_sqj[tid] = g_sq[bj * TM + tid];
    __syncthreads();

    // epilogue: D = sqi + sqj - 2*dot -> exp -> sum (skip diagonal)
    const int g = lid >> 2, tt = lid & 3;
    const bool diag = (bi == bj);
    float lsum = 0.0f;
    #pragma unroll
    for (int mi = 0; mi < 4; mi++) {
        const int rl0 = wr * 64 + mi * 16 + g;
        const int rl1 = rl0 + 8;
        const float si0 = s_sqi[rl0], si1 = s_sqi[rl1];
        #pragma unroll
        for (int ni = 0; ni < 8; ni++) {
            const int c0 = wc * 64 + ni * 8 + 2 * tt;
            const int c1 = c0 + 1;
            const float sj0 = s_sqj[c0], sj1 = s_sqj[c1];
            const float2 p0 = __half22float2(*(__half2*)&d[mi][ni][0]);
            const float2 p1 = __half22float2(*(__half2*)&d[mi][ni][1]);
            float e00 = __expf(-(si0 + sj0 - 2.0f * p0.x) * TAU_INV);
            float e01 = __expf(-(si0 + sj1 - 2.0f * p0.y) * TAU_INV);
            float e10 = __expf(-(si1 + sj0 - 2.0f * p1.x) * TAU_INV);
            float e11 = __expf(-(si1 + sj1 - 2.0f * p1.y) * TAU_INV);
            if (diag) {
                if (rl0 == c0) e00 = 0.0f;
                if (rl0 == c1) e01 = 0.0f;
                if (rl1 == c0) e10 = 0.0f;
                if (rl1 == c1) e11 = 0.0f;
            }
            lsum += (e00 + e01) + (e10 + e11);
        }
    }

    #pragma unroll
    for (int o = 16; o > 0; o >>= 1) lsum += __shfl_down_sync(0xffffffffu, lsum, o);
    if (lid == 0) s_red[wid] = lsum;
    __syncthreads();
    if (tid == 0) {
        const float bsum = (s_red[0] + s_red[1]) + (s_red[2] + s_red[3]);
        atomicAdd(&g_acc, diag ? (double)bsum : 2.0 * (double)bsum);
    }
}

// ---------------- Kernel 3: finalize ----------------
__global__ void fin_kernel(float* __restrict__ out) {
    out[0] = (float)log(g_acc / ((double)NR * (double)(NR - 1)));
}

extern "C" void kernel_launch(void* const* d_in, const int* in_sizes, int n_in,
                              void* d_out, int out_size) {
    const float* z = (const float*)d_in[0];
    float* out = (float*)d_out;

    cudaFuncSetAttribute(pair_mma_kernel,
                         cudaFuncAttributeMaxDynamicSharedMemorySize,
                         NSTG * STG_BYTES);

    prep_kernel<<<NR / 8, 256>>>(z);
    pair_mma_kernel<<<NTILES, 128, NSTG * STG_BYTES>>>();
    fin_kernel<<<1, 1>>>(out);
}

// round 13
// speedup vs baseline: 1.0861x; 1.0861x over previous
#include <cuda_runtime.h>
#include <cuda_fp16.h>
#include <stdint.h>
#include <math.h>

#define NR 8192
#define KD 512
#define TM 128
#define KC 64                      // f16 k-chunk: 128 B/row
#define NCH (KD / KC)              // 8 K-chunks
#define NB (NR / TM)               // 64 row blocks
#define NTILES (NB * (NB + 1) / 2) // 2080 upper-triangle tiles
#define ROWB 128                   // SW128-swizzled row stride
#define STG_BYTES (2 * TM * ROWB)  // A+B per stage = 32 KB
#define TAU_INV 0.01f

__device__ double g_acc;
__device__ float g_sq[NR];
__device__ __half g_zb[(size_t)NR * KD];   // f16, 8 MB

// SW128 swizzle: conflict-free 8-row x 16B-unit access for 128B rows
#define SW128(off) ((off) ^ (((off) >> 3) & 0x70))

// ---------------- helpers ----------------
__device__ __forceinline__ uint32_t smem_u32(const void* p) {
    uint32_t a;
    asm("{ .reg .u64 t; cvta.to.shared.u64 t, %1; cvt.u32.u64 %0, t; }"
        : "=r"(a) : "l"(p));
    return a;
}
__device__ __forceinline__ void cp_async16(uint32_t s, const void* g) {
    asm volatile("cp.async.cg.shared.global [%0], [%1], 16;" :: "r"(s), "l"(g));
}
#define CP_COMMIT() asm volatile("cp.async.commit_group;" ::: "memory")
#define CP_WAIT1()  asm volatile("cp.async.wait_group 1;" ::: "memory")

__device__ __forceinline__ void ldm_x4(uint32_t* r, uint32_t a) {
    asm volatile("ldmatrix.sync.aligned.m8n8.x4.shared.b16 {%0,%1,%2,%3}, [%4];"
        : "=r"(r[0]), "=r"(r[1]), "=r"(r[2]), "=r"(r[3]) : "r"(a));
}
__device__ __forceinline__ void mma_f16acc(uint32_t* d, const uint32_t* a, const uint32_t* b) {
    asm volatile(
        "mma.sync.aligned.m16n8k16.row.col.f16.f16.f16.f16 "
        "{%0,%1}, {%2,%3,%4,%5}, {%6,%7}, {%0,%1};"
        : "+r"(d[0]), "+r"(d[1])
        : "r"(a[0]), "r"(a[1]), "r"(a[2]), "r"(a[3]), "r"(b[0]), "r"(b[1]));
}

// ---------------- Kernel 1: convert to f16 + fp32 row norms (1 warp/row) ----------------
__global__ void __launch_bounds__(256) prep_kernel(const float* __restrict__ z) {
    const int w = threadIdx.x >> 5, lane = threadIdx.x & 31;
    const int row = blockIdx.x * 8 + w;
    const float4* zr = (const float4*)(z + (size_t)row * KD);
    __half2* dst = (__half2*)(g_zb + (size_t)row * KD);
    float s = 0.0f;
    #pragma unroll
    for (int i = 0; i < 4; i++) {
        const float4 v = zr[lane + 32 * i];
        s += v.x * v.x + v.y * v.y + v.z * v.z + v.w * v.w;
        dst[2 * (lane + 32 * i)]     = __floats2half2_rn(v.x, v.y);
        dst[2 * (lane + 32 * i) + 1] = __floats2half2_rn(v.z, v.w);
    }
    #pragma unroll
    for (int o = 16; o > 0; o >>= 1) s += __shfl_down_sync(0xffffffffu, s, o);
    if (lane == 0) {
        g_sq[row] = s;
        if (row == 0) g_acc = 0.0;
    }
}

// ---------------- Kernel 2: 2-stage KC=64 f16-accum HMMA GEMM ----------------
__global__ void __launch_bounds__(128) pair_mma_kernel() {
    extern __shared__ __align__(16) char dsm[];          // 2 * 32 KB
    __shared__ float s_sqi[TM], s_sqj[TM];
    __shared__ float s_red[4];

    const int tid = threadIdx.x;
    const int wid = tid >> 5;         // 0..3
    const int lid = tid & 31;
    const int wr = wid >> 1;          // warp row 0..1 (64 rows)
    const int wc = wid & 1;           // warp col 0..1 (64 cols)

    int t = blockIdx.x, bi = 0;
    while (t >= NB - bi) { t -= NB - bi; bi++; }
    const int bj = bi + t;

    const __half* Ag = g_zb + (size_t)(bi * TM) * KD;
    const __half* Bg = g_zb + (size_t)(bj * TM) * KD;

    uint32_t smA[2], smB[2];
    const uint32_t dbase = smem_u32(dsm);
    #pragma unroll
    for (int s = 0; s < 2; s++) {
        smA[s] = dbase + s * STG_BYTES;
        smB[s] = dbase + s * STG_BYTES + TM * ROWB;
    }

    // chunk = 128 rows x 128 B per matrix = 1024 x 16B units; 8 slots/thread/matrix
    auto load_chunk = [&](int kc, int st) {
        #pragma unroll
        for (int i = 0; i < 8; i++) {
            const int f = tid + (i << 7);          // 0..1023
            const int r = f >> 3, u = f & 7;
            const uint32_t so = SW128((uint32_t)r * ROWB + (uint32_t)u * 16);
            const size_t go = (size_t)r * KD + (size_t)kc * KC + (size_t)u * 8;
            cp_async16(smA[st] + so, Ag + go);
            cp_async16(smB[st] + so, Bg + go);
        }
    };

    uint32_t d[4][8][2];
    #pragma unroll
    for (int mi = 0; mi < 4; mi++)
        #pragma unroll
        for (int ni = 0; ni < 8; ni++) {
            d[mi][ni][0] = 0u;
            d[mi][ni][1] = 0u;
        }

    load_chunk(0, 0); CP_COMMIT();
    load_chunk(1, 1); CP_COMMIT();

    const int a_row = (lid & 15);
    const int a_jofs = (lid >> 4);
    const int b_row = (lid & 7) + ((lid >> 4) << 3);
    const int b_jofs = ((lid >> 3) & 1);

    for (int kc = 0; kc < NCH; kc++) {
        CP_WAIT1();
        __syncthreads();
        const int st = kc & 1;
        #pragma unroll
        for (int kk = 0; kk < 4; kk++) {           // four k=16 steps per chunk
            uint32_t afr[4][4];
            #pragma unroll
            for (int mi = 0; mi < 4; mi++) {
                const int r = wr * 64 + mi * 16 + a_row;
                ldm_x4(afr[mi], smA[st] +
                       SW128((uint32_t)r * ROWB + (uint32_t)(kk * 2 + a_jofs) * 16));
            }
            uint32_t bfr[16];
            #pragma unroll
            for (int nb = 0; nb < 4; nb++) {
                const int n = wc * 64 + nb * 16 + b_row;
                ldm_x4(bfr + nb * 4, smB[st] +
                       SW128((uint32_t)n * ROWB + (uint32_t)(kk * 2 + b_jofs) * 16));
            }
            #pragma unroll
            for (int mi = 0; mi < 4; mi++)
                #pragma unroll
                for (int ni = 0; ni < 8; ni++)
                    mma_f16acc(d[mi][ni], afr[mi], bfr + ni * 2);
        }
        __syncthreads();
        if (kc + 2 < NCH) load_chunk(kc + 2, st);
        CP_COMMIT();
    }

    s_sqi[tid] = g_sq[bi * TM + tid];
    s_sqj[tid] = g_sq[bj * TM + tid];
    __syncthreads();

    // epilogue: D = sqi + sqj - 2*dot -> exp -> sum (skip diagonal)
    const int g = lid >> 2, tt = lid & 3;
    const bool diag = (bi == bj);
    float lsum = 0.0f;
    #pragma unroll
    for (int mi = 0; mi < 4; mi++) {
        const int rl0 = wr * 64 + mi * 16 + g;
        const int rl1 = rl0 + 8;
        const float si0 = s_sqi[rl0], si1 = s_sqi[rl1];
        #pragma unroll
        for (int ni = 0; ni < 8; ni++) {
            const int c0 = wc * 64 + ni * 8 + 2 * tt;
            const int c1 = c0 + 1;
            const float sj0 = s_sqj[c0], sj1 = s_sqj[c1];
            const float2 p0 = __half22float2(*(__half2*)&d[mi][ni][0]);
            const float2 p1 = __half22float2(*(__half2*)&d[mi][ni][1]);
            float e00 = __expf(-(si0 + sj0 - 2.0f * p0.x) * TAU_INV);
            float e01 = __expf(-(si0 + sj1 - 2.0f * p0.y) * TAU_INV);
            float e10 = __expf(-(si1 + sj0 - 2.0f * p1.x) * TAU_INV);
            float e11 = __expf(-(si1 + sj1 - 2.0f * p1.y) * TAU_INV);
            if (diag) {
                if (rl0 == c0) e00 = 0.0f;
                if (rl0 == c1) e01 = 0.0f;
                if (rl1 == c0) e10 = 0.0f;
                if (rl1 == c1) e11 = 0.0f;
            }
            lsum += (e00 + e01) + (e10 + e11);
        }
    }

    #pragma unroll
    for (int o = 16; o > 0; o >>= 1) lsum += __shfl_down_sync(0xffffffffu, lsum, o);
    if (lid == 0) s_red[wid] = lsum;
    __syncthreads();
    if (tid == 0) {
        const float bsum = (s_red[0] + s_red[1]) + (s_red[2] + s_red[3]);
        atomicAdd(&g_acc, diag ? (double)bsum : 2.0 * (double)bsum);
    }
}

// ---------------- Kernel 3: finalize ----------------
__global__ void fin_kernel(float* __restrict__ out) {
    out[0] = (float)log(g_acc / ((double)NR * (double)(NR - 1)));
}

extern "C" void kernel_launch(void* const* d_in, const int* in_sizes, int n_in,
                              void* d_out, int out_size) {
    const float* z = (const float*)d_in[0];
    float* out = (float*)d_out;

    cudaFuncSetAttribute(pair_mma_kernel,
                         cudaFuncAttributeMaxDynamicSharedMemorySize,
                         2 * STG_BYTES);

    prep_kernel<<<NR / 8, 256>>>(z);
    pair_mma_kernel<<<NTILES, 128, 2 * STG_BYTES>>>();
    fin_kernel<<<1, 1>>>(out);
}